// round 3
// baseline (speedup 1.0000x reference)
#include <cuda_runtime.h>
#include <cuda_bf16.h>
#include <math.h>

#define Bn 8
#define Dn 1024
#define Gn 32
#define Kn 64
#define NPn 1024
#define NT 64        // n-rows per CTA
#define GSPLIT 8     // group interleave chunks

// Scratch (device globals; no allocation allowed)
__device__ float g_xzT[(size_t)Bn * Dn * NPn];     // 32 MB: z transposed [b][d][n]
__device__ float g_cw[Bn * Gn * Kn];               // folded coeff*mask*weight*valid

// packed dual-fp32 FMA (Blackwell f32x2; PTX-only, ptxas won't auto-fuse)
#define FMA2(acc, m, r) \
    asm("fma.rn.f32x2 %0, %1, %2, %0;" : "+l"(acc) : "l"(m), "l"(r))

#define CP_ASYNC16(dst_s32, src_g) \
    asm volatile("cp.async.cg.shared.global [%0], [%1], 16;" \
                 :: "r"(dst_s32), "l"(src_g))
#define CP_COMMIT() asm volatile("cp.async.commit_group;")

// ---------------------------------------------------------------------------
// Kernel 1 (prep): fused transpose + cw build + out zeroing.
//   grid (NPn/32, Dn/32, Bn), block (32,8).
//   xzT[b][d][n] = x[b][n][d] - xopt[b][d]
//   blocks (0, 0, b) additionally build g_cw slice for batch b and zero out[b].
// ---------------------------------------------------------------------------
__global__ void prep_kernel(const float* __restrict__ x,
                            const float* __restrict__ xopt,
                            const void*  __restrict__ vm,
                            const float* __restrict__ w,
                            const int*   __restrict__ gc,
                            float*       __restrict__ out)
{
    __shared__ float t[32][33];
    int b  = blockIdx.z;
    int n0 = blockIdx.x * 32;
    int d0 = blockIdx.y * 32;
    int tx = threadIdx.x, ty = threadIdx.y;

    #pragma unroll
    for (int j = ty; j < 32; j += 8) {
        int n = n0 + j, d = d0 + tx;
        t[j][tx] = x[((size_t)b * NPn + n) * Dn + d] - xopt[b * Dn + d];
    }
    __syncthreads();
    #pragma unroll
    for (int j = ty; j < 32; j += 8) {
        int d = d0 + j, n = n0 + tx;
        g_xzT[((size_t)b * Dn + d) * NPn + n] = t[tx][j];
    }

    if (blockIdx.x == 0 && blockIdx.y == 0) {
        int tid = ty * 32 + tx;
        __shared__ int mode;     // 1 = 4-byte bool storage, 0 = 1-byte
        if (tid == 0) {
            const unsigned int* u = (const unsigned int*)vm;
            int m4 = 1;
            for (int i = 0; i < 16; ++i) {
                unsigned int v = u[i];
                if (v != 0u && v != 1u && v != 0x3F800000u) m4 = 0;
            }
            mode = m4;
        }
        __syncthreads();
        int gcb = gc[b];
        for (int i = tid; i < Gn * Kn; i += 256) {
            int g = i >> 6;
            int k = i & 63;
            int gi = b * Gn * Kn + i;
            bool m;
            if (mode) m = (((const unsigned int*)vm)[gi] != 0u);
            else      m = (((const unsigned char*)vm)[gi] != 0);
            float cf = (float)pow(1.0e6, (double)k / 63.0);
            float wv = (g < gcb) ? w[b * Gn + g] : 0.0f;
            g_cw[gi] = m ? cf * wv : 0.0f;
        }
        for (int i = tid; i < NPn; i += 256) out[b * NPn + i] = 0.0f;
    }
}

// ---------------------------------------------------------------------------
// Kernel 2: fitness. Grid (Bn * NPn/NT, GSPLIT), block 256.
// Chunk c handles groups g = c, c+GSPLIT, ... while g < gc[b].
// Double-buffered cp.async gather of z tiles; FMA2 mainloop (2n x 8l / thread).
// CTA result atomicAdd'ed into out (out zeroed by prep).
// ---------------------------------------------------------------------------
__global__ __launch_bounds__(256) void fitness_kernel(
    const float* __restrict__ R,
    const int*   __restrict__ gidx,
    const int*   __restrict__ gc,
    float*       __restrict__ out)
{
    __shared__ float Rs[Kn * Kn];        // 16 KB
    __shared__ float zs[2][Kn * NT];     // 32 KB, [buf][k][n]
    __shared__ float fit_s[NT];

    int tid   = threadIdx.x;
    int b     = blockIdx.x >> 4;
    int n0    = (blockIdx.x & 15) * NT;
    int chunk = blockIdx.y;
    int nt    = tid & 31;
    int lt    = tid >> 5;

    int gcb = gc[b];
    int ng  = (gcb > chunk) ? ((gcb - 1 - chunk) / GSPLIT + 1) : 0;
    if (ng == 0) return;

    for (int i = tid; i < Kn * Kn; i += 256) Rs[i] = R[i];
    if (tid < NT) fit_s[tid] = 0.0f;

    // gather issue lambda: thread handles column k = p*16 + tid>>4, 16B chunk tid&15
    int kq = tid >> 4;          // 0..15
    int nq = tid & 15;          // 0..15
    unsigned int zs_base[2];
    zs_base[0] = (unsigned int)__cvta_generic_to_shared(&zs[0][0]);
    zs_base[1] = (unsigned int)__cvta_generic_to_shared(&zs[1][0]);

    #define ISSUE_GATHER(gi, buf)                                              \
    {                                                                          \
        int g_ = chunk + (gi) * GSPLIT;                                        \
        const int* ip_ = gidx + (b * Gn + g_) * Kn;                            \
        _Pragma("unroll")                                                      \
        for (int p = 0; p < 4; ++p) {                                          \
            int k_   = p * 16 + kq;                                            \
            int col_ = __ldg(ip_ + k_);                                        \
            const float* src_ =                                                \
                &g_xzT[((size_t)(b * Dn + col_)) * NPn + n0 + nq * 4];         \
            unsigned int dst_ = zs_base[buf] + (k_ * NT + nq * 4) * 4;         \
            CP_ASYNC16(dst_, src_);                                            \
        }                                                                      \
        CP_COMMIT();                                                           \
    }

    float fa0 = 0.0f, fa1 = 0.0f;

    ISSUE_GATHER(0, 0);

    for (int gi = 0; gi < ng; ++gi) {
        int buf = gi & 1;
        bool has_next = (gi + 1 < ng);
        if (has_next) ISSUE_GATHER(gi + 1, buf ^ 1);

        if (has_next) asm volatile("cp.async.wait_group 1;");
        else          asm volatile("cp.async.wait_group 0;");
        __syncthreads();

        int g = chunk + gi * GSPLIT;
        const float4* cwp = (const float4*)(g_cw + (b * Gn + g) * Kn + lt * 8);
        float4 c0 = __ldg(cwp);
        float4 c1 = __ldg(cwp + 1);
        float cw_r[8] = {c0.x, c0.y, c0.z, c0.w, c1.x, c1.y, c1.z, c1.w};

        const float* zb = &zs[buf][0];

        unsigned long long accE[4], accO[4];
        #pragma unroll
        for (int i = 0; i < 4; ++i) { accE[i] = 0ull; accO[i] = 0ull; }

        #pragma unroll 8
        for (int k = 0; k < Kn; ++k) {
            float2 z2 = *(const float2*)&zb[k * NT + nt * 2];
            unsigned long long zx2, zy2;
            asm("mov.b64 %0, {%1, %1};" : "=l"(zx2) : "f"(z2.x));
            asm("mov.b64 %0, {%1, %1};" : "=l"(zy2) : "f"(z2.y));
            const ulonglong2* rp = (const ulonglong2*)&Rs[k * Kn + lt * 8];
            ulonglong2 ra = rp[0];
            ulonglong2 rb = rp[1];
            FMA2(accE[0], zx2, ra.x);  FMA2(accE[1], zx2, ra.y);
            FMA2(accE[2], zx2, rb.x);  FMA2(accE[3], zx2, rb.y);
            FMA2(accO[0], zy2, ra.x);  FMA2(accO[1], zy2, ra.y);
            FMA2(accO[2], zy2, rb.x);  FMA2(accO[3], zy2, rb.y);
        }

        float s0 = 0.0f, s1 = 0.0f;
        #pragma unroll
        for (int j = 0; j < 4; ++j) {
            float e0 = __uint_as_float((unsigned int)(accE[j] & 0xFFFFFFFFull));
            float e1 = __uint_as_float((unsigned int)(accE[j] >> 32));
            float o0 = __uint_as_float((unsigned int)(accO[j] & 0xFFFFFFFFull));
            float o1 = __uint_as_float((unsigned int)(accO[j] >> 32));
            s0 += cw_r[2 * j] * e0 * e0 + cw_r[2 * j + 1] * e1 * e1;
            s1 += cw_r[2 * j] * o0 * o0 + cw_r[2 * j + 1] * o1 * o1;
        }
        fa0 += s0;
        fa1 += s1;

        __syncthreads();   // zs[buf] free for the prefetch two iters ahead
    }

    // Reduce 8 l-chunks (one per warp) per n via shared atomics, then global.
    atomicAdd(&fit_s[nt * 2],     fa0);
    atomicAdd(&fit_s[nt * 2 + 1], fa1);
    __syncthreads();
    if (tid < NT) {
        atomicAdd(&out[b * NPn + n0 + tid], fit_s[tid]);
    }
    #undef ISSUE_GATHER
}

// ---------------------------------------------------------------------------
// kernel_launch
// Inputs (metadata order): x, weights, xopt, R, group_indices, valid_mask,
//                          group_counts
// ---------------------------------------------------------------------------
extern "C" void kernel_launch(void* const* d_in, const int* in_sizes, int n_in,
                              void* d_out, int out_size)
{
    const float* x      = (const float*)d_in[0];
    const float* w      = (const float*)d_in[1];
    const float* xopt   = (const float*)d_in[2];
    const float* R      = (const float*)d_in[3];
    const int*   gidx   = (const int*)d_in[4];
    const void*  vmask  = (const void*)d_in[5];
    const int*   gc     = (const int*)d_in[6];
    float*       out    = (float*)d_out;

    dim3 tg(NPn / 32, Dn / 32, Bn);
    prep_kernel<<<tg, dim3(32, 8)>>>(x, xopt, vmask, w, gc, out);

    dim3 fg(Bn * (NPn / NT), GSPLIT);
    fitness_kernel<<<fg, 256>>>(R, gidx, gc, out);
}

// round 5
// speedup vs baseline: 1.8059x; 1.8059x over previous
#include <cuda_runtime.h>
#include <cuda_bf16.h>

#define Bn 8
#define Dn 1024
#define Gn 32
#define Kn 64
#define NPn 1024
#define NT 64        // n-rows per CTA
#define GSPLIT 8     // group interleave chunks

// Scratch (device global; no allocation allowed)
__device__ float g_xzT[(size_t)Bn * Dn * NPn];     // 32 MB: z transposed [b][d][n]

// packed dual-fp32 FMA (Blackwell f32x2; PTX-only, ptxas won't auto-fuse)
#define FMA2(acc, m, r) \
    asm("fma.rn.f32x2 %0, %1, %2, %0;" : "+l"(acc) : "l"(m), "l"(r))

#define CP_ASYNC16(dst_s32, src_g) \
    asm volatile("cp.async.cg.shared.global [%0], [%1], 16;" \
                 :: "r"(dst_s32), "l"(src_g))
#define CP_COMMIT() asm volatile("cp.async.commit_group;")

// ---------------------------------------------------------------------------
// Kernel 1 (prep): lean tiled transpose + out zeroing.
//   grid (NPn/32, Dn/32, Bn), block (32,8).
//   xzT[b][d][n] = x[b][n][d] - xopt[b][d]
// ---------------------------------------------------------------------------
__global__ void prep_kernel(const float* __restrict__ x,
                            const float* __restrict__ xopt,
                            float*       __restrict__ out)
{
    __shared__ float t[32][33];
    int b  = blockIdx.z;
    int n0 = blockIdx.x * 32;
    int d0 = blockIdx.y * 32;
    int tx = threadIdx.x, ty = threadIdx.y;

    #pragma unroll
    for (int j = ty; j < 32; j += 8) {
        int n = n0 + j, d = d0 + tx;
        t[j][tx] = x[((size_t)b * NPn + n) * Dn + d] - xopt[b * Dn + d];
    }
    __syncthreads();
    #pragma unroll
    for (int j = ty; j < 32; j += 8) {
        int d = d0 + j, n = n0 + tx;
        g_xzT[((size_t)b * Dn + d) * NPn + n] = t[tx][j];
    }

    if (blockIdx.x == 0 && blockIdx.y == 0) {
        int tid = ty * 32 + tx;
        for (int i = tid; i < NPn; i += 256) out[b * NPn + i] = 0.0f;
    }
}

// ---------------------------------------------------------------------------
// Kernel 2: fitness. Grid (Bn * NPn/NT, GSPLIT), block 256.
// Chunk c handles groups g = c, c+GSPLIT, ... while g < gc[b].
// Double-buffered cp.async gather of z tiles; FMA2 mainloop (2n x 8l / thread).
// cw (coeff*mask*weight) folded inline per group; coeffs via exp2f table.
// CTA result atomicAdd'ed into out (out zeroed by prep).
// ---------------------------------------------------------------------------
__global__ __launch_bounds__(256, 4) void fitness_kernel(
    const float* __restrict__ R,
    const int*   __restrict__ gidx,
    const int*   __restrict__ gc,
    const void*  __restrict__ vm,
    const float* __restrict__ w,
    float*       __restrict__ out)
{
    __shared__ float Rs[Kn * Kn];        // 16 KB
    __shared__ float zs[2][Kn * NT];     // 32 KB, [buf][k][n]
    __shared__ float fit_s[NT];
    __shared__ float cf_s[Kn];

    int tid   = threadIdx.x;
    int b     = blockIdx.x >> 4;
    int n0    = (blockIdx.x & 15) * NT;
    int chunk = blockIdx.y;
    int nt    = tid & 31;
    int lt    = tid >> 5;

    int gcb = gc[b];
    int ng  = (gcb > chunk) ? ((gcb - 1 - chunk) / GSPLIT + 1) : 0;
    if (ng == 0) return;

    // valid_mask storage-width detect (uniform across threads, ~16 L2 loads)
    int mode4 = 1;
    #pragma unroll
    for (int i = 0; i < 16; ++i) {
        unsigned int v = __ldg((const unsigned int*)vm + i);
        if (v != 0u && v != 1u && v != 0x3F800000u) mode4 = 0;
    }

    for (int i = tid; i < Kn * Kn; i += 256) Rs[i] = R[i];
    if (tid < NT) fit_s[tid] = 0.0f;
    if (tid < Kn) cf_s[tid] = exp2f((float)tid * (19.931568569324174f / 63.0f));
    __syncthreads();   // cf_s/fit_s/Rs visible to ALL warps before group loop
                       // (R4 bug: warps 2-7 read cf_s pre-barrier -> 1.2e-2 err)

    // gather: thread handles column k = p*16 + tid>>4, 16B n-chunk tid&15
    int kq = tid >> 4;          // 0..15
    int nq = tid & 15;          // 0..15
    unsigned int zs_base[2];
    zs_base[0] = (unsigned int)__cvta_generic_to_shared(&zs[0][0]);
    zs_base[1] = (unsigned int)__cvta_generic_to_shared(&zs[1][0]);

    #define ISSUE_GATHER(gi, buf)                                              \
    {                                                                          \
        int g_ = chunk + (gi) * GSPLIT;                                        \
        const int* ip_ = gidx + (b * Gn + g_) * Kn;                            \
        _Pragma("unroll")                                                      \
        for (int p = 0; p < 4; ++p) {                                          \
            int k_   = p * 16 + kq;                                            \
            int col_ = __ldg(ip_ + k_);                                        \
            const float* src_ =                                                \
                &g_xzT[((size_t)(b * Dn + col_)) * NPn + n0 + nq * 4];         \
            unsigned int dst_ = zs_base[buf] + (k_ * NT + nq * 4) * 4;         \
            CP_ASYNC16(dst_, src_);                                            \
        }                                                                      \
        CP_COMMIT();                                                           \
    }

    float fa0 = 0.0f, fa1 = 0.0f;

    ISSUE_GATHER(0, 0);

    for (int gi = 0; gi < ng; ++gi) {
        int buf = gi & 1;
        bool has_next = (gi + 1 < ng);
        if (has_next) ISSUE_GATHER(gi + 1, buf ^ 1);

        // fold cw for this group's 8 l-values; LDGs overlap the cp.async wait
        int g = chunk + gi * GSPLIT;
        float wv = __ldg(w + b * Gn + g);
        float cw_r[8];
        {
            int base = (b * Gn + g) * Kn + lt * 8;
            #pragma unroll
            for (int j = 0; j < 8; ++j) {
                bool m;
                if (mode4) m = (__ldg((const unsigned int*)vm + base + j) != 0u);
                else       m = (__ldg((const unsigned char*)vm + base + j) != 0);
                cw_r[j] = m ? cf_s[lt * 8 + j] * wv : 0.0f;
            }
        }

        if (has_next) asm volatile("cp.async.wait_group 1;");
        else          asm volatile("cp.async.wait_group 0;");
        __syncthreads();

        const float* zb = &zs[buf][0];

        unsigned long long accE[4], accO[4];
        #pragma unroll
        for (int i = 0; i < 4; ++i) { accE[i] = 0ull; accO[i] = 0ull; }

        #pragma unroll 8
        for (int k = 0; k < Kn; ++k) {
            float2 z2 = *(const float2*)&zb[k * NT + nt * 2];
            unsigned long long zx2, zy2;
            asm("mov.b64 %0, {%1, %1};" : "=l"(zx2) : "f"(z2.x));
            asm("mov.b64 %0, {%1, %1};" : "=l"(zy2) : "f"(z2.y));
            const ulonglong2* rp = (const ulonglong2*)&Rs[k * Kn + lt * 8];
            ulonglong2 ra = rp[0];
            ulonglong2 rb = rp[1];
            FMA2(accE[0], zx2, ra.x);  FMA2(accE[1], zx2, ra.y);
            FMA2(accE[2], zx2, rb.x);  FMA2(accE[3], zx2, rb.y);
            FMA2(accO[0], zy2, ra.x);  FMA2(accO[1], zy2, ra.y);
            FMA2(accO[2], zy2, rb.x);  FMA2(accO[3], zy2, rb.y);
        }

        float s0 = 0.0f, s1 = 0.0f;
        #pragma unroll
        for (int j = 0; j < 4; ++j) {
            float e0 = __uint_as_float((unsigned int)(accE[j] & 0xFFFFFFFFull));
            float e1 = __uint_as_float((unsigned int)(accE[j] >> 32));
            float o0 = __uint_as_float((unsigned int)(accO[j] & 0xFFFFFFFFull));
            float o1 = __uint_as_float((unsigned int)(accO[j] >> 32));
            s0 += cw_r[2 * j] * e0 * e0 + cw_r[2 * j + 1] * e1 * e1;
            s1 += cw_r[2 * j] * o0 * o0 + cw_r[2 * j + 1] * o1 * o1;
        }
        fa0 += s0;
        fa1 += s1;

        __syncthreads();   // zs[buf] free for the prefetch two iters ahead
    }

    // Reduce 8 l-chunks (one per warp) per n via shared atomics, then global.
    atomicAdd(&fit_s[nt * 2],     fa0);
    atomicAdd(&fit_s[nt * 2 + 1], fa1);
    __syncthreads();
    if (tid < NT) {
        atomicAdd(&out[b * NPn + n0 + tid], fit_s[tid]);
    }
    #undef ISSUE_GATHER
}

// ---------------------------------------------------------------------------
// kernel_launch
// Inputs (metadata order): x, weights, xopt, R, group_indices, valid_mask,
//                          group_counts
// ---------------------------------------------------------------------------
extern "C" void kernel_launch(void* const* d_in, const int* in_sizes, int n_in,
                              void* d_out, int out_size)
{
    const float* x      = (const float*)d_in[0];
    const float* w      = (const float*)d_in[1];
    const float* xopt   = (const float*)d_in[2];
    const float* R      = (const float*)d_in[3];
    const int*   gidx   = (const int*)d_in[4];
    const void*  vmask  = (const void*)d_in[5];
    const int*   gc     = (const int*)d_in[6];
    float*       out    = (float*)d_out;

    dim3 tg(NPn / 32, Dn / 32, Bn);
    prep_kernel<<<tg, dim3(32, 8)>>>(x, xopt, out);

    dim3 fg(Bn * (NPn / NT), GSPLIT);
    fitness_kernel<<<fg, 256>>>(R, gidx, gc, vmask, w, out);
}

// round 6
// speedup vs baseline: 1.8217x; 1.0088x over previous
#include <cuda_runtime.h>
#include <cuda_bf16.h>

#define Bn 8
#define Dn 1024
#define Gn 32
#define Kn 64
#define NPn 1024
#define NTILE 128    // n-rows per CTA
#define KC 32        // k-chunk (pipeline stage)
#define GSPLIT 8     // group interleave chunks

// Scratch (device global; no allocation allowed)
__device__ float g_xzT[(size_t)Bn * Dn * NPn];     // 32 MB: z transposed [b][d][n]

// packed dual-fp32 FMA (Blackwell f32x2; PTX-only, ptxas won't auto-fuse)
#define FMA2(acc, m, r) \
    asm("fma.rn.f32x2 %0, %1, %2, %0;" : "+l"(acc) : "l"(m), "l"(r))

#define CP_ASYNC16(dst_s32, src_g) \
    asm volatile("cp.async.cg.shared.global [%0], [%1], 16;" \
                 :: "r"(dst_s32), "l"(src_g))
#define CP_COMMIT() asm volatile("cp.async.commit_group;")

// ---------------------------------------------------------------------------
// Kernel 1 (prep): lean tiled transpose + out zeroing.
// ---------------------------------------------------------------------------
__global__ void prep_kernel(const float* __restrict__ x,
                            const float* __restrict__ xopt,
                            float*       __restrict__ out)
{
    __shared__ float t[32][33];
    int b  = blockIdx.z;
    int n0 = blockIdx.x * 32;
    int d0 = blockIdx.y * 32;
    int tx = threadIdx.x, ty = threadIdx.y;

    #pragma unroll
    for (int j = ty; j < 32; j += 8) {
        int n = n0 + j, d = d0 + tx;
        t[j][tx] = x[((size_t)b * NPn + n) * Dn + d] - xopt[b * Dn + d];
    }
    __syncthreads();
    #pragma unroll
    for (int j = ty; j < 32; j += 8) {
        int d = d0 + j, n = n0 + tx;
        g_xzT[((size_t)b * Dn + d) * NPn + n] = t[tx][j];
    }

    if (blockIdx.x == 0 && blockIdx.y == 0) {
        int tid = ty * 32 + tx;
        for (int i = tid; i < NPn; i += 256) out[b * NPn + i] = 0.0f;
    }
}

// ---------------------------------------------------------------------------
// Kernel 2: fitness. Grid (Bn * NPn/NTILE = 64, GSPLIT), block 256, ONE wave.
// Thread tile 4n x 8l (16 FMA2 accs). Pipeline stage = 32-k half-chunk.
//   nt = tid & 31 -> n quad (4*nt)   lt = tid >> 5 -> l range [lt*8, +8)
// ---------------------------------------------------------------------------
__global__ __launch_bounds__(256, 3) void fitness_kernel(
    const float* __restrict__ R,
    const int*   __restrict__ gidx,
    const int*   __restrict__ gc,
    const void*  __restrict__ vm,
    const float* __restrict__ w,
    float*       __restrict__ out)
{
    __shared__ float Rs[Kn * Kn];          // 16 KB
    __shared__ float zs[2][KC * NTILE];    // 32 KB, [buf][k_local][n]
    __shared__ float fit_s[NTILE];
    __shared__ float cf_s[Kn];

    int tid   = threadIdx.x;
    int b     = blockIdx.x >> 3;
    int n0    = (blockIdx.x & 7) * NTILE;
    int chunk = blockIdx.y;
    int nt    = tid & 31;
    int lt    = tid >> 5;

    int gcb = gc[b];
    int ng  = (gcb > chunk) ? ((gcb - 1 - chunk) / GSPLIT + 1) : 0;
    if (ng == 0) return;

    // valid_mask storage-width detect (uniform across threads)
    int mode4 = 1;
    #pragma unroll
    for (int i = 0; i < 16; ++i) {
        unsigned int v = __ldg((const unsigned int*)vm + i);
        if (v != 0u && v != 1u && v != 0x3F800000u) mode4 = 0;
    }

    for (int i = tid; i < Kn * Kn; i += 256) Rs[i] = R[i];
    if (tid < NTILE) fit_s[tid] = 0.0f;
    if (tid < Kn) cf_s[tid] = exp2f((float)tid * (19.931568569324174f / 63.0f));
    __syncthreads();   // cf_s/fit_s/Rs visible to ALL warps before use

    // gather: thread owns k_local = tid>>3 (0..31), n-16B-chunks (tid&7)+8j
    int kq = tid >> 3;          // 0..31
    int nq = tid & 7;           // 0..7
    unsigned int zs_base[2];
    zs_base[0] = (unsigned int)__cvta_generic_to_shared(&zs[0][0]);
    zs_base[1] = (unsigned int)__cvta_generic_to_shared(&zs[1][0]);

    // stage s: group = chunk + (s>>1)*GSPLIT, half h = s&1 (k = h*32 + kl)
    #define ISSUE(s, buf)                                                      \
    {                                                                          \
        int g_ = chunk + ((s) >> 1) * GSPLIT;                                  \
        int k_ = ((s) & 1) * KC + kq;                                          \
        int col_ = __ldg(gidx + (b * Gn + g_) * Kn + k_);                      \
        const float* src_ = &g_xzT[((size_t)(b * Dn + col_)) * NPn + n0];      \
        _Pragma("unroll")                                                      \
        for (int j = 0; j < 4; ++j) {                                          \
            int nof_ = (nq + 8 * j) * 4;                                       \
            CP_ASYNC16(zs_base[buf] + (kq * NTILE + nof_) * 4, src_ + nof_);   \
        }                                                                      \
        CP_COMMIT();                                                           \
    }

    float fs[4] = {0.0f, 0.0f, 0.0f, 0.0f};
    float cw_r[8];
    unsigned long long acc[4][4];

    int ts = 2 * ng;
    ISSUE(0, 0);

    for (int s = 0; s < ts; ++s) {
        int buf = s & 1;
        int h   = s & 1;
        bool has_next = (s + 1 < ts);
        if (has_next) ISSUE(s + 1, buf ^ 1);

        if (h == 0) {
            // new group: fold cw (LDGs overlap the cp.async wait), reset accs
            int g = chunk + (s >> 1) * GSPLIT;
            float wv = __ldg(w + b * Gn + g);
            int base = (b * Gn + g) * Kn + lt * 8;
            #pragma unroll
            for (int j = 0; j < 8; ++j) {
                bool m;
                if (mode4) m = (__ldg((const unsigned int*)vm + base + j) != 0u);
                else       m = (__ldg((const unsigned char*)vm + base + j) != 0);
                cw_r[j] = m ? cf_s[lt * 8 + j] * wv : 0.0f;
            }
            #pragma unroll
            for (int i = 0; i < 4; ++i)
                #pragma unroll
                for (int j = 0; j < 4; ++j) acc[i][j] = 0ull;
        }

        if (has_next) asm volatile("cp.async.wait_group 1;");
        else          asm volatile("cp.async.wait_group 0;");
        __syncthreads();

        const float* zb = &zs[buf][0];
        const float* rrow = &Rs[h * KC * Kn + lt * 8];

        #pragma unroll 8
        for (int kl = 0; kl < KC; ++kl) {
            float4 z4 = *(const float4*)&zb[kl * NTILE + nt * 4];
            const ulonglong2* rp = (const ulonglong2*)&rrow[kl * Kn];
            ulonglong2 ra = rp[0];
            ulonglong2 rb = rp[1];
            unsigned long long z2[4];
            asm("mov.b64 %0, {%1, %1};" : "=l"(z2[0]) : "f"(z4.x));
            asm("mov.b64 %0, {%1, %1};" : "=l"(z2[1]) : "f"(z4.y));
            asm("mov.b64 %0, {%1, %1};" : "=l"(z2[2]) : "f"(z4.z));
            asm("mov.b64 %0, {%1, %1};" : "=l"(z2[3]) : "f"(z4.w));
            #pragma unroll
            for (int i = 0; i < 4; ++i) {
                FMA2(acc[i][0], z2[i], ra.x);
                FMA2(acc[i][1], z2[i], ra.y);
                FMA2(acc[i][2], z2[i], rb.x);
                FMA2(acc[i][3], z2[i], rb.y);
            }
        }
        __syncthreads();   // zb free for the stage issued two ahead

        if (h == 1) {
            // group done: fold squares with cw into per-n partials
            #pragma unroll
            for (int i = 0; i < 4; ++i) {
                float s0 = 0.0f;
                #pragma unroll
                for (int j = 0; j < 4; ++j) {
                    float lo = __uint_as_float((unsigned int)(acc[i][j] & 0xFFFFFFFFull));
                    float hi = __uint_as_float((unsigned int)(acc[i][j] >> 32));
                    s0 += cw_r[2 * j] * lo * lo + cw_r[2 * j + 1] * hi * hi;
                }
                fs[i] += s0;
            }
        }
    }

    // reduce 8 l-chunks (one per warp) per n via shared atomics, then global
    #pragma unroll
    for (int i = 0; i < 4; ++i) atomicAdd(&fit_s[nt * 4 + i], fs[i]);
    __syncthreads();
    for (int i = tid; i < NTILE; i += 256)
        atomicAdd(&out[b * NPn + n0 + i], fit_s[i]);
    #undef ISSUE
}

// ---------------------------------------------------------------------------
// kernel_launch
// Inputs (metadata order): x, weights, xopt, R, group_indices, valid_mask,
//                          group_counts
// ---------------------------------------------------------------------------
extern "C" void kernel_launch(void* const* d_in, const int* in_sizes, int n_in,
                              void* d_out, int out_size)
{
    const float* x      = (const float*)d_in[0];
    const float* w      = (const float*)d_in[1];
    const float* xopt   = (const float*)d_in[2];
    const float* R      = (const float*)d_in[3];
    const int*   gidx   = (const int*)d_in[4];
    const void*  vmask  = (const void*)d_in[5];
    const int*   gc     = (const int*)d_in[6];
    float*       out    = (float*)d_out;

    dim3 tg(NPn / 32, Dn / 32, Bn);
    prep_kernel<<<tg, dim3(32, 8)>>>(x, xopt, out);

    dim3 fg(Bn * (NPn / NTILE), GSPLIT);
    fitness_kernel<<<fg, 256>>>(R, gidx, gc, vmask, w, out);
}

// round 7
// speedup vs baseline: 2.1347x; 1.1718x over previous
#include <cuda_runtime.h>
#include <cuda_bf16.h>

#define Bn 8
#define Dn 1024
#define Gn 32
#define Kn 64
#define NPn 1024
#define NTILE 128     // n-rows per work unit
#define KC 32         // k-chunk (pipeline stage = half a group)
#define GRID 444      // 148 SMs * 3 CTA/SM -> exactly one wave

// Scratch (device globals; no allocation allowed)
__device__ float g_xzT[(size_t)Bn * Dn * NPn];   // 32 MB: z transposed [b][d][n]
__device__ int   g_items[Bn * Gn];               // packed (b<<8)|g, valid groups
__device__ int   g_nitems;

// packed dual-fp32 FMA (Blackwell f32x2; PTX-only, ptxas won't auto-fuse)
#define FMA2(acc, m, r) \
    asm("fma.rn.f32x2 %0, %1, %2, %0;" : "+l"(acc) : "l"(m), "l"(r))

#define CP_ASYNC16(dst_s32, src_g) \
    asm volatile("cp.async.cg.shared.global [%0], [%1], 16;" \
                 :: "r"(dst_s32), "l"(src_g))
#define CP_COMMIT() asm volatile("cp.async.commit_group;")

// ---------------------------------------------------------------------------
// Kernel 1 (prep): lean tiled transpose + out zeroing + work-list build.
// ---------------------------------------------------------------------------
__global__ void prep_kernel(const float* __restrict__ x,
                            const float* __restrict__ xopt,
                            const int*   __restrict__ gc,
                            float*       __restrict__ out)
{
    __shared__ float t[32][33];
    int b  = blockIdx.z;
    int n0 = blockIdx.x * 32;
    int d0 = blockIdx.y * 32;
    int tx = threadIdx.x, ty = threadIdx.y;

    #pragma unroll
    for (int j = ty; j < 32; j += 8) {
        int n = n0 + j, d = d0 + tx;
        t[j][tx] = x[((size_t)b * NPn + n) * Dn + d] - xopt[b * Dn + d];
    }
    __syncthreads();
    #pragma unroll
    for (int j = ty; j < 32; j += 8) {
        int d = d0 + j, n = n0 + tx;
        g_xzT[((size_t)b * Dn + d) * NPn + n] = t[tx][j];
    }

    if (blockIdx.x == 0 && blockIdx.y == 0) {
        int tid = ty * 32 + tx;
        for (int i = tid; i < NPn; i += 256) out[b * NPn + i] = 0.0f;
        if (b == 0 && tid == 0) {
            int m = 0;
            for (int bb = 0; bb < Bn; ++bb) {
                int c = gc[bb];
                for (int g = 0; g < c; ++g) g_items[m++] = (bb << 8) | g;
            }
            g_nitems = m;
        }
    }
}

// ---------------------------------------------------------------------------
// Kernel 2: fitness. Grid GRID=444 (one wave), block 256.
// CTA c processes units c, c+GRID, ... ; unit = item*8 + tile.
// Stage = 32-k half of one unit; triple-buffered, one barrier per stage.
// Thread tile 4n x 8l:  nt = tid&31 -> n quad,  lt = tid>>5 -> l octet.
// Dynamic smem: Rs (16KB) | zs[3] (48KB) | cf (256B).
// ---------------------------------------------------------------------------
__global__ __launch_bounds__(256, 3) void fitness_kernel(
    const float* __restrict__ R,
    const int*   __restrict__ gidx,
    const void*  __restrict__ vm,
    const float* __restrict__ w,
    float*       __restrict__ out)
{
    extern __shared__ char sm[];
    float* Rs   = (float*)sm;                       // 16 KB
    float* zs   = (float*)(sm + 16384);             // 3 * 16 KB
    float* cf_s = (float*)(sm + 16384 + 49152);     // 256 B

    int tid = threadIdx.x;
    int cta = blockIdx.x;
    int nt  = tid & 31;
    int lt  = tid >> 5;

    int nunits = 8 * g_nitems;
    int mu = (cta < nunits) ? ((nunits - 1 - cta) / GRID + 1) : 0;
    if (mu == 0) return;
    int ts = 2 * mu;

    // valid_mask storage-width detect (uniform across threads)
    int mode4 = 1;
    #pragma unroll
    for (int i = 0; i < 16; ++i) {
        unsigned int v = __ldg((const unsigned int*)vm + i);
        if (v != 0u && v != 1u && v != 0x3F800000u) mode4 = 0;
    }

    for (int i = tid; i < Kn * Kn; i += 256) Rs[i] = R[i];
    if (tid < Kn) cf_s[tid] = exp2f((float)tid * (19.931568569324174f / 63.0f));
    __syncthreads();   // Rs/cf_s visible to all warps before any use

    // gather: thread owns k_local = tid>>3 (0..31), 16B n-chunks (tid&7)+8j
    int kq = tid >> 3;
    int nq = tid & 7;
    unsigned int zb0 = (unsigned int)__cvta_generic_to_shared(zs);

    // stage j: unit = cta + (j>>1)*GRID, half = j&1
    #define ISSUE(j)                                                           \
    {                                                                          \
        int u_  = cta + ((j) >> 1) * GRID;                                     \
        int it_ = g_items[u_ >> 3];                                            \
        int b_  = it_ >> 8, g_ = it_ & 255, n0_ = (u_ & 7) * NTILE;            \
        int k_  = ((j) & 1) * KC + kq;                                         \
        int col_ = __ldg(gidx + (b_ * Gn + g_) * Kn + k_);                     \
        const float* src_ = &g_xzT[((size_t)(b_ * Dn + col_)) * NPn + n0_];    \
        unsigned int db_ = zb0 + ((j) % 3) * 16384 + kq * (NTILE * 4);         \
        _Pragma("unroll")                                                      \
        for (int jj = 0; jj < 4; ++jj) {                                       \
            int nof_ = (nq + 8 * jj) * 4;                                      \
            CP_ASYNC16(db_ + nof_ * 4, src_ + nof_);                           \
        }                                                                      \
        CP_COMMIT();                                                           \
    }

    float cw_r[8];
    unsigned long long acc[4][4];
    int ub = 0, un0 = 0;

    ISSUE(0);
    if (ts > 1) ISSUE(1);

    for (int j = 0; j < ts; ++j) {
        int h = j & 1;

        if (j == ts - 1) asm volatile("cp.async.wait_group 0;");
        else             asm volatile("cp.async.wait_group 1;");
        __syncthreads();            // stage j's buffer filled for everyone;
                                    // also: buffer (j+2)%3 free (read in j-1)
        if (j + 2 < ts) ISSUE(j + 2);

        if (h == 0) {
            // new unit: decode, fold cw (LDGs overlap compute below), reset accs
            int u  = cta + (j >> 1) * GRID;
            int it = g_items[u >> 3];
            ub  = it >> 8;
            un0 = (u & 7) * NTILE;
            int g = it & 255;
            float wv = __ldg(w + ub * Gn + g);
            int base = (ub * Gn + g) * Kn + lt * 8;
            #pragma unroll
            for (int jj = 0; jj < 8; ++jj) {
                bool m;
                if (mode4) m = (__ldg((const unsigned int*)vm + base + jj) != 0u);
                else       m = (__ldg((const unsigned char*)vm + base + jj) != 0);
                cw_r[jj] = m ? cf_s[lt * 8 + jj] * wv : 0.0f;
            }
            #pragma unroll
            for (int i = 0; i < 4; ++i)
                #pragma unroll
                for (int jj = 0; jj < 4; ++jj) acc[i][jj] = 0ull;
        }

        const float* zb   = zs + (j % 3) * (KC * NTILE);
        const float* rrow = &Rs[h * KC * Kn + lt * 8];

        #pragma unroll 8
        for (int kl = 0; kl < KC; ++kl) {
            float4 z4 = *(const float4*)&zb[kl * NTILE + nt * 4];
            const ulonglong2* rp = (const ulonglong2*)&rrow[kl * Kn];
            ulonglong2 ra = rp[0];
            ulonglong2 rb = rp[1];
            unsigned long long z2[4];
            asm("mov.b64 %0, {%1, %1};" : "=l"(z2[0]) : "f"(z4.x));
            asm("mov.b64 %0, {%1, %1};" : "=l"(z2[1]) : "f"(z4.y));
            asm("mov.b64 %0, {%1, %1};" : "=l"(z2[2]) : "f"(z4.z));
            asm("mov.b64 %0, {%1, %1};" : "=l"(z2[3]) : "f"(z4.w));
            #pragma unroll
            for (int i = 0; i < 4; ++i) {
                FMA2(acc[i][0], z2[i], ra.x);
                FMA2(acc[i][1], z2[i], ra.y);
                FMA2(acc[i][2], z2[i], rb.x);
                FMA2(acc[i][3], z2[i], rb.y);
            }
        }

        if (h == 1) {
            // unit done: fold squares with cw, reduce straight to gmem (RED)
            #pragma unroll
            for (int i = 0; i < 4; ++i) {
                float s0 = 0.0f;
                #pragma unroll
                for (int jj = 0; jj < 4; ++jj) {
                    float lo = __uint_as_float((unsigned int)(acc[i][jj] & 0xFFFFFFFFull));
                    float hi = __uint_as_float((unsigned int)(acc[i][jj] >> 32));
                    s0 += cw_r[2 * jj] * lo * lo + cw_r[2 * jj + 1] * hi * hi;
                }
                atomicAdd(&out[ub * NPn + un0 + nt * 4 + i], s0);
            }
        }
    }
    #undef ISSUE
}

// ---------------------------------------------------------------------------
// kernel_launch
// Inputs (metadata order): x, weights, xopt, R, group_indices, valid_mask,
//                          group_counts
// ---------------------------------------------------------------------------
extern "C" void kernel_launch(void* const* d_in, const int* in_sizes, int n_in,
                              void* d_out, int out_size)
{
    const float* x      = (const float*)d_in[0];
    const float* w      = (const float*)d_in[1];
    const float* xopt   = (const float*)d_in[2];
    const float* R      = (const float*)d_in[3];
    const int*   gidx   = (const int*)d_in[4];
    const void*  vmask  = (const void*)d_in[5];
    const int*   gc     = (const int*)d_in[6];
    float*       out    = (float*)d_out;

    const int smem_bytes = 16384 + 49152 + 256;
    cudaFuncSetAttribute(fitness_kernel,
                         cudaFuncAttributeMaxDynamicSharedMemorySize, smem_bytes);

    dim3 tg(NPn / 32, Dn / 32, Bn);
    prep_kernel<<<tg, dim3(32, 8)>>>(x, xopt, gc, out);

    fitness_kernel<<<GRID, 256, smem_bytes>>>(R, gidx, vmask, w, out);
}